// round 12
// baseline (speedup 1.0000x reference)
#include <cuda_runtime.h>
#include <cuda_fp16.h>
#include <math.h>
#include <stdint.h>

// Problem constants
constexpr int Bc   = 2;
constexpr int Nn   = 5456;
constexpr int Sc   = 5456;
constexpr int Hc   = 8;
constexpr int Lc   = 5;
constexpr int Pc   = 4;
constexpr int Kin  = 256;
constexpr int Mtot = Bc * Nn;          // 10912
constexpr int NPT  = Lc * Pc;          // 20
constexpr int OFFC = Hc * NPT * 3;     // 480
constexpr int ATTC = Hc * NPT;         // 160
constexpr int OPRJ = 256 + OFFC + ATTC; // 896: [val | off | attn]

// GEMM tile config: BM=64, BN=64, full K=256 resident in smem.
constexpr int AST = 40;                 // halves per row per 32-col stage (32+8 pad)
constexpr int GEMM_SMEM = 2 * (8 * 64 * AST) * 2;  // A + B, 81920 bytes

// Scratch (static device globals — allocation-free)
__device__ __half g_valh[(size_t)Bc * Hc * Sc * 32];   // [B,H,S,32] fp16
__device__ float g_off[(size_t)Mtot * OFFC];
__device__ float g_logit[(size_t)Mtot * ATTC];
__device__ __half gA_in[(size_t)Mtot * Kin];           // fp16 in_feats
__device__ __half gA_sf[(size_t)Mtot * Kin];           // fp16 sample_feats
__device__ __half gA_w [(size_t)Mtot * Kin];           // fp16 weighted
__device__ __half gW_all[OPRJ * Kin];                  // [val|off|attn] rows
__device__ __half gW_out[256 * Kin];

// ---------------------------------------------------------------------------
// PTX helpers
// ---------------------------------------------------------------------------
__device__ __forceinline__ void cp16(uint32_t dst, const void* src, int sz) {
    asm volatile("cp.async.cg.shared.global [%0], [%1], 16, %2;\n"
                 :: "r"(dst), "l"(src), "r"(sz));
}
__device__ __forceinline__ void cp_commit() {
    asm volatile("cp.async.commit_group;\n");
}
__device__ __forceinline__ void cp_wait0() {
    asm volatile("cp.async.wait_group 0;\n");
}
__device__ __forceinline__ void ldsm4(uint32_t* r, uint32_t a) {
    asm volatile("ldmatrix.sync.aligned.m8n8.x4.shared.b16 {%0,%1,%2,%3}, [%4];\n"
                 : "=r"(r[0]), "=r"(r[1]), "=r"(r[2]), "=r"(r[3]) : "r"(a));
}
__device__ __forceinline__ void mma16816(float* c, const uint32_t* a,
                                         uint32_t b0, uint32_t b1) {
    asm volatile(
        "mma.sync.aligned.m16n8k16.row.col.f32.f16.f16.f32 "
        "{%0,%1,%2,%3},{%4,%5,%6,%7},{%8,%9},{%0,%1,%2,%3};\n"
        : "+f"(c[0]), "+f"(c[1]), "+f"(c[2]), "+f"(c[3])
        : "r"(a[0]), "r"(a[1]), "r"(a[2]), "r"(a[3]), "r"(b0), "r"(b1));
}
// Packed fp32x2 FMA (Blackwell, PTX ISA 8.6+): a = v * w + a (exact fp32)
__device__ __forceinline__ void ffma2(float2& a, float2 v, float2 w) {
    asm("fma.rn.f32x2 %0, %1, %2, %0;"
        : "+l"(reinterpret_cast<unsigned long long&>(a))
        : "l"(reinterpret_cast<unsigned long long&>(v)),
          "l"(reinterpret_cast<unsigned long long&>(w)));
}

// ---------------------------------------------------------------------------
// Convert both activation matrices fp32 -> fp16 (vectorized, one launch)
// ---------------------------------------------------------------------------
__global__ __launch_bounds__(256) void conv_a(
    const float4* __restrict__ in, const float4* __restrict__ sf)
{
    int i = blockIdx.x * 256 + threadIdx.x;   // grid covers Mtot*64 float4s
    {
        float4 a = in[i];
        __half2 h0 = __floats2half2_rn(a.x, a.y);
        __half2 h1 = __floats2half2_rn(a.z, a.w);
        uint2 p;
        p.x = *(uint32_t*)&h0; p.y = *(uint32_t*)&h1;
        ((uint2*)gA_in)[i] = p;
    }
    {
        float4 a = sf[i];
        __half2 h0 = __floats2half2_rn(a.x, a.y);
        __half2 h1 = __floats2half2_rn(a.z, a.w);
        uint2 p;
        p.x = *(uint32_t*)&h0; p.y = *(uint32_t*)&h1;
        ((uint2*)gA_sf)[i] = p;
    }
}

// ---------------------------------------------------------------------------
// Convert all weights fp32 -> fp16 (vectorized float4 path)
// ---------------------------------------------------------------------------
__global__ __launch_bounds__(256) void conv_w(
    const float4* __restrict__ Wval, const float4* __restrict__ Woff,
    const float4* __restrict__ Wattn, const float4* __restrict__ Wout)
{
    int i = blockIdx.x * 256 + threadIdx.x;   // 1152 * 64 float4s
    int row = i >> 6, k4 = i & 63;
    float4 a;
    uint2* dst;
    if (row < 256)       { a = Wval [(size_t)row * 64 + k4];         dst = (uint2*)gW_all + i; }
    else if (row < 736)  { a = Woff [(size_t)(row - 256) * 64 + k4]; dst = (uint2*)gW_all + i; }
    else if (row < OPRJ) { a = Wattn[(size_t)(row - 736) * 64 + k4]; dst = (uint2*)gW_all + i; }
    else                 { a = Wout [(size_t)(row - OPRJ) * 64 + k4];
                           dst = (uint2*)gW_out + ((size_t)(row - OPRJ) * 64 + k4); }
    __half2 h0 = __floats2half2_rn(a.x, a.y);
    __half2 h1 = __floats2half2_rn(a.z, a.w);
    uint2 p;
    p.x = *(uint32_t*)&h0; p.y = *(uint32_t*)&h1;
    *dst = p;
}

// ---------------------------------------------------------------------------
// fp16 tensor-core GEMM, full-K-resident tile (BM=64, BN=64, K=256).
// One batch of cp.asyncs, one wait, one sync, then 16 uninterrupted k16
// mma steps. 8 warps: warpM (0..3) x 16 rows, warpN (0..1) x 32 cols.
// MODE 0 (projection, O=896): A per CTA = (col<256 ? A0=sf : A1=in);
//   o<256 -> g_valh fp16 (+bias_val), o<736 -> g_off, else -> g_logit
// MODE 1 (output, O=256): A = A0 (gA_w), Cout fp32 (+bias_val)
// ---------------------------------------------------------------------------
template <int MODE>
__global__ __launch_bounds__(256) void gemm_f16(
    const __half* __restrict__ A0, const __half* __restrict__ A1,
    const __half* __restrict__ W,
    const float* __restrict__ bias_val, const float* __restrict__ bias_off,
    const float* __restrict__ bias_attn,
    float* __restrict__ Cout, int M, int O)
{
    extern __shared__ __half smem[];
    __half* As = smem;                    // 8 stages x 64 rows x AST
    __half* Bs = smem + 8 * 64 * AST;

    const int tid  = threadIdx.x;
    const int warp = tid >> 5;
    const int lane = tid & 31;
    const int warpM = warp >> 1;      // 0..3 (16 rows each)
    const int warpN = warp & 1;       // 0..1 (32 cols each)
    const int row0 = blockIdx.y * 64;
    const int col0 = blockIdx.x * 64;

    const __half* __restrict__ A = (MODE == 0 && col0 >= 256) ? A1 : A0;

    const uint32_t sAs = (uint32_t)__cvta_generic_to_shared(As);
    const uint32_t sBs = (uint32_t)__cvta_generic_to_shared(Bs);

    // Load the ENTIRE 64x256 A tile and 64x256 B tile.
    // 2048 16B-chunks each; 8 per thread per matrix.
#pragma unroll
    for (int p = 0; p < 8; p++) {
        int idx = tid + p * 256;          // 0..2047
        int r  = idx >> 5;                // row 0..63
        int cc = idx & 31;                // chunk-in-row 0..31 (8 halves each)
        int stage = cc >> 2;              // k-stage 0..7 (32 cols per stage)
        int c = (cc & 3) * 8;             // col within stage
        uint32_t soff = (uint32_t)((stage * 64 + r) * AST + c) * 2;
        {
            int gm = row0 + r;
            const __half* src = A + (size_t)(gm < M ? gm : M - 1) * Kin + cc * 8;
            cp16(sAs + soff, src, (gm < M) ? 16 : 0);
        }
        {
            int go = col0 + r;
            const __half* src = W + (size_t)(go < O ? go : O - 1) * Kin + cc * 8;
            cp16(sBs + soff, src, (go < O) ? 16 : 0);
        }
    }
    cp_commit();
    cp_wait0();
    __syncthreads();

    float acc[4][4] = {};

#pragma unroll
    for (int t = 0; t < 16; t++) {        // k16 steps
        const int stage = t >> 1;
        const int cs = (t & 1) * 16 + (lane >> 4) * 8;
        uint32_t afr[4], bfr[2][4];
        {
            uint32_t addr = sAs +
                (uint32_t)((stage * 64 + warpM * 16 + (lane & 15)) * AST + cs) * 2;
            ldsm4(afr, addr);
        }
#pragma unroll
        for (int nt2 = 0; nt2 < 2; nt2++) {
            uint32_t addr = sBs +
                (uint32_t)((stage * 64 + warpN * 32 + nt2 * 16 + (lane & 15)) * AST + cs) * 2;
            ldsm4(bfr[nt2], addr);
        }
#pragma unroll
        for (int nt = 0; nt < 4; nt++) {
            uint32_t b0 = (nt & 1) ? bfr[nt >> 1][1] : bfr[nt >> 1][0];
            uint32_t b1 = (nt & 1) ? bfr[nt >> 1][3] : bfr[nt >> 1][2];
            mma16816(acc[nt], afr, b0, b1);
        }
    }

    // Epilogue
#pragma unroll
    for (int nt = 0; nt < 4; nt++) {
#pragma unroll
        for (int e = 0; e < 4; e++) {
            int m = row0 + warpM * 16 + (lane >> 2) + (e >= 2 ? 8 : 0);
            int o = col0 + warpN * 32 + nt * 8 + 2 * (lane & 3) + (e & 1);
            if (m >= M || o >= O) continue;
            float v = acc[nt][e];
            if (MODE == 0) {
                if (o < 256) {
                    int b = m / Sc, ss = m % Sc;
                    int hh = o >> 5, d = o & 31;
                    g_valh[(((size_t)(b * Hc + hh)) * Sc + ss) * 32 + d] =
                        __float2half(v + bias_val[o]);
                } else if (o < 736) {
                    g_off[(size_t)m * OFFC + (o - 256)] = v + bias_off[o - 256];
                } else {
                    g_logit[(size_t)m * ATTC + (o - 736)] = v + bias_attn[o - 736];
                }
            } else {
                Cout[(size_t)m * O + o] = v + bias_val[o];
            }
        }
    }
}

// ---------------------------------------------------------------------------
// Fused sampler (unchanged from R11: __launch_bounds__(256, 8), FFMA2,
// single-exp softmax).
// ---------------------------------------------------------------------------
__global__ __launch_bounds__(256, 8) void sample_kernel(
    const float* __restrict__ priors,
    const int* __restrict__ map_shapes,
    const int* __restrict__ start_ids)
{
    const int m = blockIdx.x;
    const int b = (m >= Nn) ? 1 : 0;

    __shared__ int2  s_tab[ATTC][8];
    __shared__ float s_logit[ATTC];
    __shared__ float s_exp[ATTC];
    __shared__ float s_wh[Lc][2];
    __shared__ int   s_start[Lc];

    const int tid = threadIdx.x;
    if (tid < Lc) {
        s_wh[tid][0] = (float)map_shapes[tid * 2 + 1];  // W
        s_wh[tid][1] = (float)map_shapes[tid * 2 + 0];  // H
        s_start[tid] = start_ids[tid];
    }
    for (int i = tid; i < ATTC; i += 256) s_logit[i] = g_logit[(size_t)m * ATTC + i];
    __syncthreads();

    if (tid < ATTC) {
        const int h = tid / NPT;
        float mx = -1e30f;
        for (int j = 0; j < NPT; j++) mx = fmaxf(mx, s_logit[h * NPT + j]);
        s_exp[tid] = __expf(s_logit[tid] - mx);
    }
    __syncthreads();

    if (tid < ATTC) {
        const int h  = tid / NPT;
        const int lp = tid % NPT;
        const int l  = lp / Pc;
        const float ox = g_off[(size_t)m * OFFC + tid * 3 + 0];
        const float oy = g_off[(size_t)m * OFFC + tid * 3 + 1];
        const float oz = g_off[(size_t)m * OFFC + tid * 3 + 2];
        const float Wl = s_wh[l][0], Hl = s_wh[l][1];
        const float px = priors[((size_t)m * Lc + l) * 2 + 0];
        const float py = priors[((size_t)m * Lc + l) * 2 + 1];
        const float lx = px + ox / Wl;
        const float ly = py + oy / Hl;
        const float lz = (float)l * (1.0f / (Lc - 1)) + oz;

        float sum = 0.f;
        for (int j = 0; j < NPT; j++) sum += s_exp[h * NPT + j];
        const float a = s_exp[tid] / sum;

        float z = fminf(fmaxf(lz, 0.f), 1.f) * (float)(Lc - 1);
        int z0 = min((int)z, Lc - 2);
        float wz = z - (float)z0;

#pragma unroll
        for (int q = 0; q < 2; q++) {
            const int lvl = z0 + q;
            const float wl = a * (q ? wz : (1.f - wz));
            const float Wf = s_wh[lvl][0], Hf = s_wh[lvl][1];
            const int Wi = (int)Wf, Hi = (int)Hf;
            const int offb = s_start[lvl];
            const float x = lx * Wf - 0.5f;
            const float y = ly * Hf - 0.5f;
            const float x0f = floorf(x), y0f = floorf(y);
            const float dx = x - x0f, dy = y - y0f;
            const int x0 = (int)x0f, y0 = (int)y0f;

            const float cw[4] = {(1.f - dx) * (1.f - dy), dx * (1.f - dy),
                                 (1.f - dx) * dy,          dx * dy};
            const int cx[4] = {x0, x0 + 1, x0, x0 + 1};
            const int cy[4] = {y0, y0, y0 + 1, y0 + 1};
#pragma unroll
            for (int c = 0; c < 4; c++) {
                const bool valid = (cx[c] >= 0) & (cx[c] < Wi) & (cy[c] >= 0) & (cy[c] < Hi);
                const int idx = valid ? (offb + cy[c] * Wi + cx[c]) : 0;
                const float w = valid ? (wl * cw[c]) : 0.f;
                s_tab[tid][q * 4 + c] = make_int2(idx << 6, __float_as_int(w));
            }
        }
    }
    __syncthreads();

    const int warp = tid >> 5;              // head
    const int lane = tid & 31;
    const int sub  = lane >> 2;             // corner 0..7
    const int ch   = lane & 3;              // 16B channel group

    const char* __restrict__ vbase =
        (const char*)g_valh + (size_t)(b * Hc + warp) * Sc * 64 + ch * 16;

    float2 acc[4] = {};
#pragma unroll
    for (int p = 0; p < NPT; p++) {
        const int2 e = s_tab[warp * NPT + p][sub];
        const float w = __int_as_float(e.y);
        if (w != 0.f) {
            const uint4 raw = __ldg((const uint4*)(vbase + e.x));
            const float2 wv = make_float2(w, w);
            ffma2(acc[0], __half22float2(*(const __half2*)&raw.x), wv);
            ffma2(acc[1], __half22float2(*(const __half2*)&raw.y), wv);
            ffma2(acc[2], __half22float2(*(const __half2*)&raw.z), wv);
            ffma2(acc[3], __half22float2(*(const __half2*)&raw.w), wv);
        }
    }
#pragma unroll
    for (int d = 4; d < 32; d <<= 1) {
#pragma unroll
        for (int j = 0; j < 4; j++) {
            acc[j].x += __shfl_xor_sync(0xFFFFFFFFu, acc[j].x, d);
            acc[j].y += __shfl_xor_sync(0xFFFFFFFFu, acc[j].y, d);
        }
    }
    if (lane < 4) {
        __half2 h0 = __floats2half2_rn(acc[0].x, acc[0].y);
        __half2 h1 = __floats2half2_rn(acc[1].x, acc[1].y);
        __half2 h2 = __floats2half2_rn(acc[2].x, acc[2].y);
        __half2 h3 = __floats2half2_rn(acc[3].x, acc[3].y);
        uint4 pack;
        pack.x = *(uint32_t*)&h0;
        pack.y = *(uint32_t*)&h1;
        pack.z = *(uint32_t*)&h2;
        pack.w = *(uint32_t*)&h3;
        ((uint4*)gA_w)[(size_t)m * 32 + warp * 4 + ch] = pack;
    }
}

// ---------------------------------------------------------------------------
// kernel_launch
// ---------------------------------------------------------------------------
extern "C" void kernel_launch(void* const* d_in, const int* in_sizes, int n_in,
                              void* d_out, int out_size)
{
    const float* in_feats  = (const float*)d_in[0];
    const float* priors    = (const float*)d_in[1];
    const float* sfeats    = (const float*)d_in[2];
    const float* W_off     = (const float*)d_in[3];
    const float* b_off     = (const float*)d_in[4];
    const float* W_attn    = (const float*)d_in[5];
    const float* b_attn    = (const float*)d_in[6];
    const float* W_val     = (const float*)d_in[7];
    const float* b_val     = (const float*)d_in[8];
    const float* W_out     = (const float*)d_in[9];
    const float* b_out     = (const float*)d_in[10];
    const int*   shapes    = (const int*)d_in[11];
    const int*   start_ids = (const int*)d_in[12];

    __half *pA_in, *pA_sf, *pA_w, *pW_all, *pW_out;
    cudaGetSymbolAddress((void**)&pA_in,  gA_in);
    cudaGetSymbolAddress((void**)&pA_sf,  gA_sf);
    cudaGetSymbolAddress((void**)&pA_w,   gA_w);
    cudaGetSymbolAddress((void**)&pW_all, gW_all);
    cudaGetSymbolAddress((void**)&pW_out, gW_out);

    // Allow 80KB dynamic smem for the full-K GEMM tiles (idempotent host call).
    cudaFuncSetAttribute(gemm_f16<0>, cudaFuncAttributeMaxDynamicSharedMemorySize, GEMM_SMEM);
    cudaFuncSetAttribute(gemm_f16<1>, cudaFuncAttributeMaxDynamicSharedMemorySize, GEMM_SMEM);

    // fp32 -> fp16 conversions
    conv_a<<<Mtot / 4, 256>>>((const float4*)in_feats, (const float4*)sfeats);
    conv_w<<<288, 256>>>((const float4*)W_val, (const float4*)W_off,
                         (const float4*)W_attn, (const float4*)W_out);

    const int gridM = (Mtot + 63) / 64;   // 171

    // Combined projection GEMM: [val | off | attn], O=896
    gemm_f16<0><<<dim3(OPRJ / 64, gridM), 256, GEMM_SMEM>>>(
        pA_sf, pA_in, pW_all, b_val, b_off, b_attn, nullptr, Mtot, OPRJ);
    // Fused sampler -> gA_w (fp16)
    sample_kernel<<<Mtot, 256>>>(priors, shapes, start_ids);
    // Output projection -> d_out (fp32)
    gemm_f16<1><<<dim3(4, gridM), 256, GEMM_SMEM>>>(
        pA_w, nullptr, pW_out, b_out, nullptr, nullptr, (float*)d_out, Mtot, 256);
}

// round 13
// speedup vs baseline: 1.1109x; 1.1109x over previous
#include <cuda_runtime.h>
#include <cuda_fp16.h>
#include <math.h>
#include <stdint.h>

// Problem constants
constexpr int Bc   = 2;
constexpr int Nn   = 5456;
constexpr int Sc   = 5456;
constexpr int Hc   = 8;
constexpr int Lc   = 5;
constexpr int Pc   = 4;
constexpr int Kin  = 256;
constexpr int Mtot = Bc * Nn;          // 10912
constexpr int NPT  = Lc * Pc;          // 20
constexpr int OFFC = Hc * NPT * 3;     // 480
constexpr int ATTC = Hc * NPT;         // 160
constexpr int OPRJ = 256 + OFFC + ATTC; // 896: [val | off | attn]

// Scratch (static device globals — allocation-free)
__device__ __half g_valh[(size_t)Bc * Hc * Sc * 32];   // [B,H,S,32] fp16
__device__ float g_off[(size_t)Mtot * OFFC];
__device__ float g_logit[(size_t)Mtot * ATTC];
__device__ __half gA_in[(size_t)Mtot * Kin];           // fp16 in_feats
__device__ __half gA_sf[(size_t)Mtot * Kin];           // fp16 sample_feats
__device__ __half gA_w [(size_t)Mtot * Kin];           // fp16 weighted
__device__ __half gW_all[OPRJ * Kin];                  // [val|off|attn] rows
__device__ __half gW_out[256 * Kin];

// ---------------------------------------------------------------------------
// PTX helpers
// ---------------------------------------------------------------------------
__device__ __forceinline__ void cp16(uint32_t dst, const void* src, int sz) {
    asm volatile("cp.async.cg.shared.global [%0], [%1], 16, %2;\n"
                 :: "r"(dst), "l"(src), "r"(sz));
}
__device__ __forceinline__ void cp_commit() {
    asm volatile("cp.async.commit_group;\n");
}
__device__ __forceinline__ void cp_wait2() {
    asm volatile("cp.async.wait_group 2;\n");
}
__device__ __forceinline__ void ldsm4(uint32_t* r, uint32_t a) {
    asm volatile("ldmatrix.sync.aligned.m8n8.x4.shared.b16 {%0,%1,%2,%3}, [%4];\n"
                 : "=r"(r[0]), "=r"(r[1]), "=r"(r[2]), "=r"(r[3]) : "r"(a));
}
__device__ __forceinline__ void mma16816(float* c, const uint32_t* a,
                                         uint32_t b0, uint32_t b1) {
    asm volatile(
        "mma.sync.aligned.m16n8k16.row.col.f32.f16.f16.f32 "
        "{%0,%1,%2,%3},{%4,%5,%6,%7},{%8,%9},{%0,%1,%2,%3};\n"
        : "+f"(c[0]), "+f"(c[1]), "+f"(c[2]), "+f"(c[3])
        : "r"(a[0]), "r"(a[1]), "r"(a[2]), "r"(a[3]), "r"(b0), "r"(b1));
}
// Packed fp32x2 FMA (Blackwell, PTX ISA 8.6+): a = v * w + a (exact fp32)
__device__ __forceinline__ void ffma2(float2& a, float2 v, float2 w) {
    asm("fma.rn.f32x2 %0, %1, %2, %0;"
        : "+l"(reinterpret_cast<unsigned long long&>(a))
        : "l"(reinterpret_cast<unsigned long long&>(v)),
          "l"(reinterpret_cast<unsigned long long&>(w)));
}

// ---------------------------------------------------------------------------
// Convert both activation matrices fp32 -> fp16 (vectorized, one launch)
// ---------------------------------------------------------------------------
__global__ __launch_bounds__(256) void conv_a(
    const float4* __restrict__ in, const float4* __restrict__ sf)
{
    int i = blockIdx.x * 256 + threadIdx.x;   // grid covers Mtot*64 float4s
    {
        float4 a = in[i];
        __half2 h0 = __floats2half2_rn(a.x, a.y);
        __half2 h1 = __floats2half2_rn(a.z, a.w);
        uint2 p;
        p.x = *(uint32_t*)&h0; p.y = *(uint32_t*)&h1;
        ((uint2*)gA_in)[i] = p;
    }
    {
        float4 a = sf[i];
        __half2 h0 = __floats2half2_rn(a.x, a.y);
        __half2 h1 = __floats2half2_rn(a.z, a.w);
        uint2 p;
        p.x = *(uint32_t*)&h0; p.y = *(uint32_t*)&h1;
        ((uint2*)gA_sf)[i] = p;
    }
}

// ---------------------------------------------------------------------------
// Convert all weights fp32 -> fp16 (vectorized float4 path)
// ---------------------------------------------------------------------------
__global__ __launch_bounds__(256) void conv_w(
    const float4* __restrict__ Wval, const float4* __restrict__ Woff,
    const float4* __restrict__ Wattn, const float4* __restrict__ Wout)
{
    int i = blockIdx.x * 256 + threadIdx.x;   // 1152 * 64 float4s
    int row = i >> 6, k4 = i & 63;
    float4 a;
    uint2* dst;
    if (row < 256)       { a = Wval [(size_t)row * 64 + k4];         dst = (uint2*)gW_all + i; }
    else if (row < 736)  { a = Woff [(size_t)(row - 256) * 64 + k4]; dst = (uint2*)gW_all + i; }
    else if (row < OPRJ) { a = Wattn[(size_t)(row - 736) * 64 + k4]; dst = (uint2*)gW_all + i; }
    else                 { a = Wout [(size_t)(row - OPRJ) * 64 + k4];
                           dst = (uint2*)gW_out + ((size_t)(row - OPRJ) * 64 + k4); }
    __half2 h0 = __floats2half2_rn(a.x, a.y);
    __half2 h1 = __floats2half2_rn(a.z, a.w);
    uint2 p;
    p.x = *(uint32_t*)&h0; p.y = *(uint32_t*)&h1;
    *dst = p;
}

// ---------------------------------------------------------------------------
// fp16 tensor-core GEMM: BM=64, BN=64, BK=32, 3-stage cp.async pipeline,
// 128 threads (4 warps, 2x2 warp grid, warp tile 32x32 -> ldsm:mma = 1:2).
// ~70 regs / 30KB smem -> ~7 CTAs/SM (vs 3 for the 256-thread BM=128 config)
// for much better latency hiding on this small-K latency-bound GEMM.
// MODE 0 (projection, O=896): A per CTA = (col<256 ? A0=sf : A1=in);
//   o<256 -> g_valh fp16 (+bias_val), o<736 -> g_off, else -> g_logit
// MODE 1 (output, O=256): A = A0 (gA_w), Cout fp32 (+bias_val)
// ---------------------------------------------------------------------------
template <int MODE>
__global__ __launch_bounds__(128) void gemm_f16(
    const __half* __restrict__ A0, const __half* __restrict__ A1,
    const __half* __restrict__ W,
    const float* __restrict__ bias_val, const float* __restrict__ bias_off,
    const float* __restrict__ bias_attn,
    float* __restrict__ Cout, int M, int O)
{
    constexpr int AST = 40;   // half row stride (32 + 8 pad)
    __shared__ __half As[3][64 * AST];
    __shared__ __half Bs[3][64 * AST];

    const int tid  = threadIdx.x;
    const int warp = tid >> 5;
    const int lane = tid & 31;
    const int warpM = warp >> 1;      // 0..1 (32 rows each)
    const int warpN = warp & 1;       // 0..1 (32 cols each)
    const int row0 = blockIdx.y * 64;
    const int col0 = blockIdx.x * 64;

    const __half* __restrict__ A = (MODE == 0 && col0 >= 256) ? A1 : A0;

    const uint32_t sAs = (uint32_t)__cvta_generic_to_shared(&As[0][0]);
    const uint32_t sBs = (uint32_t)__cvta_generic_to_shared(&Bs[0][0]);
    constexpr uint32_t STAGE = 64 * AST * 2;   // bytes per stage

    auto load_stage = [&](int kt, int s) {
        const int k0 = kt * 32;
        // A: 64 rows x 4 x 16B chunks = 256 ops, 2 per thread
#pragma unroll
        for (int p = 0; p < 2; p++) {
            int idx = tid + p * 128;
            int r = idx >> 2, c = idx & 3;
            int gm = row0 + r;
            const __half* src = A + (size_t)(gm < M ? gm : M - 1) * Kin + k0 + c * 8;
            uint32_t dst = sAs + s * STAGE + (uint32_t)(r * AST + c * 8) * 2;
            cp16(dst, src, (gm < M) ? 16 : 0);
        }
        // B: 64 rows x 4 chunks = 256 ops, 2 per thread
#pragma unroll
        for (int p = 0; p < 2; p++) {
            int idx = tid + p * 128;
            int r = idx >> 2, c = idx & 3;
            int go = col0 + r;
            const __half* src = W + (size_t)(go < O ? go : O - 1) * Kin + k0 + c * 8;
            uint32_t dst = sBs + s * STAGE + (uint32_t)(r * AST + c * 8) * 2;
            cp16(dst, src, (go < O) ? 16 : 0);
        }
    };

    float acc[2][4][4] = {};

    load_stage(0, 0); cp_commit();
    load_stage(1, 1); cp_commit();

    constexpr int NKT = Kin / 32;   // 8
    for (int kt = 0; kt < NKT; kt++) {
        const int s = kt % 3;
        if (kt + 2 < NKT) load_stage(kt + 2, (kt + 2) % 3);
        cp_commit();
        cp_wait2();
        __syncthreads();

        const uint32_t aBase = sAs + s * STAGE;
        const uint32_t bBase = sBs + s * STAGE;
#pragma unroll
        for (int h = 0; h < 2; h++) {
            uint32_t afr[2][4], bfr[2][4];
#pragma unroll
            for (int mt = 0; mt < 2; mt++) {
                uint32_t addr = aBase +
                    (uint32_t)((warpM * 32 + mt * 16 + (lane & 15)) * AST +
                               h * 16 + (lane >> 4) * 8) * 2;
                ldsm4(afr[mt], addr);
            }
#pragma unroll
            for (int nt2 = 0; nt2 < 2; nt2++) {
                uint32_t addr = bBase +
                    (uint32_t)((warpN * 32 + nt2 * 16 + (lane & 15)) * AST +
                               h * 16 + (lane >> 4) * 8) * 2;
                ldsm4(bfr[nt2], addr);
            }
#pragma unroll
            for (int mt = 0; mt < 2; mt++)
#pragma unroll
                for (int nt = 0; nt < 4; nt++) {
                    uint32_t b0 = (nt & 1) ? bfr[nt >> 1][1] : bfr[nt >> 1][0];
                    uint32_t b1 = (nt & 1) ? bfr[nt >> 1][3] : bfr[nt >> 1][2];
                    mma16816(acc[mt][nt], afr[mt], b0, b1);
                }
        }
        __syncthreads();
    }

#pragma unroll
    for (int mt = 0; mt < 2; mt++) {
#pragma unroll
        for (int nt = 0; nt < 4; nt++) {
#pragma unroll
            for (int e = 0; e < 4; e++) {
                int m = row0 + warpM * 32 + mt * 16 + (lane >> 2) + (e >= 2 ? 8 : 0);
                int o = col0 + warpN * 32 + nt * 8 + 2 * (lane & 3) + (e & 1);
                if (m >= M || o >= O) continue;
                float v = acc[mt][nt][e];
                if (MODE == 0) {
                    if (o < 256) {
                        int b = m / Sc, ss = m % Sc;
                        int hh = o >> 5, d = o & 31;
                        g_valh[(((size_t)(b * Hc + hh)) * Sc + ss) * 32 + d] =
                            __float2half(v + bias_val[o]);
                    } else if (o < 736) {
                        g_off[(size_t)m * OFFC + (o - 256)] = v + bias_off[o - 256];
                    } else {
                        g_logit[(size_t)m * ATTC + (o - 736)] = v + bias_attn[o - 736];
                    }
                } else {
                    Cout[(size_t)m * O + o] = v + bias_val[o];
                }
            }
        }
    }
}

// ---------------------------------------------------------------------------
// Fused sampler (unchanged from R11: __launch_bounds__(256, 8), FFMA2,
// single-exp softmax). Converged at ~90us, L1-wavefront bound.
// ---------------------------------------------------------------------------
__global__ __launch_bounds__(256, 8) void sample_kernel(
    const float* __restrict__ priors,
    const int* __restrict__ map_shapes,
    const int* __restrict__ start_ids)
{
    const int m = blockIdx.x;
    const int b = (m >= Nn) ? 1 : 0;

    __shared__ int2  s_tab[ATTC][8];
    __shared__ float s_logit[ATTC];
    __shared__ float s_exp[ATTC];
    __shared__ float s_wh[Lc][2];
    __shared__ int   s_start[Lc];

    const int tid = threadIdx.x;
    if (tid < Lc) {
        s_wh[tid][0] = (float)map_shapes[tid * 2 + 1];  // W
        s_wh[tid][1] = (float)map_shapes[tid * 2 + 0];  // H
        s_start[tid] = start_ids[tid];
    }
    for (int i = tid; i < ATTC; i += 256) s_logit[i] = g_logit[(size_t)m * ATTC + i];
    __syncthreads();

    if (tid < ATTC) {
        const int h = tid / NPT;
        float mx = -1e30f;
        for (int j = 0; j < NPT; j++) mx = fmaxf(mx, s_logit[h * NPT + j]);
        s_exp[tid] = __expf(s_logit[tid] - mx);
    }
    __syncthreads();

    if (tid < ATTC) {
        const int h  = tid / NPT;
        const int lp = tid % NPT;
        const int l  = lp / Pc;
        const float ox = g_off[(size_t)m * OFFC + tid * 3 + 0];
        const float oy = g_off[(size_t)m * OFFC + tid * 3 + 1];
        const float oz = g_off[(size_t)m * OFFC + tid * 3 + 2];
        const float Wl = s_wh[l][0], Hl = s_wh[l][1];
        const float px = priors[((size_t)m * Lc + l) * 2 + 0];
        const float py = priors[((size_t)m * Lc + l) * 2 + 1];
        const float lx = px + ox / Wl;
        const float ly = py + oy / Hl;
        const float lz = (float)l * (1.0f / (Lc - 1)) + oz;

        float sum = 0.f;
        for (int j = 0; j < NPT; j++) sum += s_exp[h * NPT + j];
        const float a = s_exp[tid] / sum;

        float z = fminf(fmaxf(lz, 0.f), 1.f) * (float)(Lc - 1);
        int z0 = min((int)z, Lc - 2);
        float wz = z - (float)z0;

#pragma unroll
        for (int q = 0; q < 2; q++) {
            const int lvl = z0 + q;
            const float wl = a * (q ? wz : (1.f - wz));
            const float Wf = s_wh[lvl][0], Hf = s_wh[lvl][1];
            const int Wi = (int)Wf, Hi = (int)Hf;
            const int offb = s_start[lvl];
            const float x = lx * Wf - 0.5f;
            const float y = ly * Hf - 0.5f;
            const float x0f = floorf(x), y0f = floorf(y);
            const float dx = x - x0f, dy = y - y0f;
            const int x0 = (int)x0f, y0 = (int)y0f;

            const float cw[4] = {(1.f - dx) * (1.f - dy), dx * (1.f - dy),
                                 (1.f - dx) * dy,          dx * dy};
            const int cx[4] = {x0, x0 + 1, x0, x0 + 1};
            const int cy[4] = {y0, y0, y0 + 1, y0 + 1};
#pragma unroll
            for (int c = 0; c < 4; c++) {
                const bool valid = (cx[c] >= 0) & (cx[c] < Wi) & (cy[c] >= 0) & (cy[c] < Hi);
                const int idx = valid ? (offb + cy[c] * Wi + cx[c]) : 0;
                const float w = valid ? (wl * cw[c]) : 0.f;
                s_tab[tid][q * 4 + c] = make_int2(idx << 6, __float_as_int(w));
            }
        }
    }
    __syncthreads();

    const int warp = tid >> 5;              // head
    const int lane = tid & 31;
    const int sub  = lane >> 2;             // corner 0..7
    const int ch   = lane & 3;              // 16B channel group

    const char* __restrict__ vbase =
        (const char*)g_valh + (size_t)(b * Hc + warp) * Sc * 64 + ch * 16;

    float2 acc[4] = {};
#pragma unroll
    for (int p = 0; p < NPT; p++) {
        const int2 e = s_tab[warp * NPT + p][sub];
        const float w = __int_as_float(e.y);
        if (w != 0.f) {
            const uint4 raw = __ldg((const uint4*)(vbase + e.x));
            const float2 wv = make_float2(w, w);
            ffma2(acc[0], __half22float2(*(const __half2*)&raw.x), wv);
            ffma2(acc[1], __half22float2(*(const __half2*)&raw.y), wv);
            ffma2(acc[2], __half22float2(*(const __half2*)&raw.z), wv);
            ffma2(acc[3], __half22float2(*(const __half2*)&raw.w), wv);
        }
    }
#pragma unroll
    for (int d = 4; d < 32; d <<= 1) {
#pragma unroll
        for (int j = 0; j < 4; j++) {
            acc[j].x += __shfl_xor_sync(0xFFFFFFFFu, acc[j].x, d);
            acc[j].y += __shfl_xor_sync(0xFFFFFFFFu, acc[j].y, d);
        }
    }
    if (lane < 4) {
        __half2 h0 = __floats2half2_rn(acc[0].x, acc[0].y);
        __half2 h1 = __floats2half2_rn(acc[1].x, acc[1].y);
        __half2 h2 = __floats2half2_rn(acc[2].x, acc[2].y);
        __half2 h3 = __floats2half2_rn(acc[3].x, acc[3].y);
        uint4 pack;
        pack.x = *(uint32_t*)&h0;
        pack.y = *(uint32_t*)&h1;
        pack.z = *(uint32_t*)&h2;
        pack.w = *(uint32_t*)&h3;
        ((uint4*)gA_w)[(size_t)m * 32 + warp * 4 + ch] = pack;
    }
}

// ---------------------------------------------------------------------------
// kernel_launch
// ---------------------------------------------------------------------------
extern "C" void kernel_launch(void* const* d_in, const int* in_sizes, int n_in,
                              void* d_out, int out_size)
{
    const float* in_feats  = (const float*)d_in[0];
    const float* priors    = (const float*)d_in[1];
    const float* sfeats    = (const float*)d_in[2];
    const float* W_off     = (const float*)d_in[3];
    const float* b_off     = (const float*)d_in[4];
    const float* W_attn    = (const float*)d_in[5];
    const float* b_attn    = (const float*)d_in[6];
    const float* W_val     = (const float*)d_in[7];
    const float* b_val     = (const float*)d_in[8];
    const float* W_out     = (const float*)d_in[9];
    const float* b_out     = (const float*)d_in[10];
    const int*   shapes    = (const int*)d_in[11];
    const int*   start_ids = (const int*)d_in[12];

    __half *pA_in, *pA_sf, *pA_w, *pW_all, *pW_out;
    cudaGetSymbolAddress((void**)&pA_in,  gA_in);
    cudaGetSymbolAddress((void**)&pA_sf,  gA_sf);
    cudaGetSymbolAddress((void**)&pA_w,   gA_w);
    cudaGetSymbolAddress((void**)&pW_all, gW_all);
    cudaGetSymbolAddress((void**)&pW_out, gW_out);

    // fp32 -> fp16 conversions
    conv_a<<<Mtot / 4, 256>>>((const float4*)in_feats, (const float4*)sfeats);
    conv_w<<<288, 256>>>((const float4*)W_val, (const float4*)W_off,
                         (const float4*)W_attn, (const float4*)W_out);

    const int gridM = (Mtot + 63) / 64;   // 171

    // Combined projection GEMM: [val | off | attn], O=896
    gemm_f16<0><<<dim3(OPRJ / 64, gridM), 128>>>(
        pA_sf, pA_in, pW_all, b_val, b_off, b_attn, nullptr, Mtot, OPRJ);
    // Fused sampler -> gA_w (fp16)
    sample_kernel<<<Mtot, 256>>>(priors, shapes, start_ids);
    // Output projection -> d_out (fp32)
    gemm_f16<1><<<dim3(4, gridM), 128>>>(
        pA_w, nullptr, pW_out, b_out, nullptr, nullptr, (float*)d_out, Mtot, 256);
}

// round 14
// speedup vs baseline: 1.2067x; 1.0863x over previous
#include <cuda_runtime.h>
#include <cuda_fp16.h>
#include <math.h>
#include <stdint.h>

// Problem constants
constexpr int Bc   = 2;
constexpr int Nn   = 5456;
constexpr int Sc   = 5456;
constexpr int Hc   = 8;
constexpr int Lc   = 5;
constexpr int Pc   = 4;
constexpr int Kin  = 256;
constexpr int Mtot = Bc * Nn;          // 10912
constexpr int NPT  = Lc * Pc;          // 20
constexpr int OFFC = Hc * NPT * 3;     // 480
constexpr int ATTC = Hc * NPT;         // 160
constexpr int OPRJ = 256 + OFFC + ATTC; // 896: [val | off | attn]

// Scratch (static device globals — allocation-free)
__device__ __half g_valh[(size_t)Bc * Hc * Sc * 32];   // [B,H,S,32] fp16
__device__ float g_off[(size_t)Mtot * OFFC];
__device__ float g_logit[(size_t)Mtot * ATTC];
__device__ __half gA_in[(size_t)Mtot * Kin];           // fp16 in_feats
__device__ __half gA_sf[(size_t)Mtot * Kin];           // fp16 sample_feats
__device__ __half gA_w [(size_t)Mtot * Kin];           // fp16 weighted
__device__ __half gW_all[OPRJ * Kin];                  // [val|off|attn] rows
__device__ __half gW_out[256 * Kin];

// ---------------------------------------------------------------------------
// PTX helpers
// ---------------------------------------------------------------------------
__device__ __forceinline__ void cp16(uint32_t dst, const void* src, int sz) {
    asm volatile("cp.async.cg.shared.global [%0], [%1], 16, %2;\n"
                 :: "r"(dst), "l"(src), "r"(sz));
}
__device__ __forceinline__ void cp_commit() {
    asm volatile("cp.async.commit_group;\n");
}
__device__ __forceinline__ void cp_wait2() {
    asm volatile("cp.async.wait_group 2;\n");
}
__device__ __forceinline__ void ldsm4(uint32_t* r, uint32_t a) {
    asm volatile("ldmatrix.sync.aligned.m8n8.x4.shared.b16 {%0,%1,%2,%3}, [%4];\n"
                 : "=r"(r[0]), "=r"(r[1]), "=r"(r[2]), "=r"(r[3]) : "r"(a));
}
__device__ __forceinline__ void mma16816(float* c, const uint32_t* a,
                                         uint32_t b0, uint32_t b1) {
    asm volatile(
        "mma.sync.aligned.m16n8k16.row.col.f32.f16.f16.f32 "
        "{%0,%1,%2,%3},{%4,%5,%6,%7},{%8,%9},{%0,%1,%2,%3};\n"
        : "+f"(c[0]), "+f"(c[1]), "+f"(c[2]), "+f"(c[3])
        : "r"(a[0]), "r"(a[1]), "r"(a[2]), "r"(a[3]), "r"(b0), "r"(b1));
}
// Packed fp32x2 FMA (Blackwell, PTX ISA 8.6+): a = v * w + a (exact fp32)
__device__ __forceinline__ void ffma2(float2& a, float2 v, float2 w) {
    asm("fma.rn.f32x2 %0, %1, %2, %0;"
        : "+l"(reinterpret_cast<unsigned long long&>(a))
        : "l"(reinterpret_cast<unsigned long long&>(v)),
          "l"(reinterpret_cast<unsigned long long&>(w)));
}

// ---------------------------------------------------------------------------
// Fused conversion: activations (blocks [0, Mtot/4)) + weights (rest).
// Activation blocks: each thread converts one float4 from each of in/sf.
// Weight blocks: one float4 from [Wval|Woff|Wattn|Wout].
// ---------------------------------------------------------------------------
constexpr int CONV_A_BLOCKS = Mtot / 4;          // 2728
constexpr int CONV_W_BLOCKS = (1152 * 64) / 256; // 288
__global__ __launch_bounds__(256) void conv_all(
    const float4* __restrict__ in, const float4* __restrict__ sf,
    const float4* __restrict__ Wval, const float4* __restrict__ Woff,
    const float4* __restrict__ Wattn, const float4* __restrict__ Wout)
{
    if (blockIdx.x < CONV_A_BLOCKS) {
        int i = blockIdx.x * 256 + threadIdx.x;
        {
            float4 a = in[i];
            __half2 h0 = __floats2half2_rn(a.x, a.y);
            __half2 h1 = __floats2half2_rn(a.z, a.w);
            uint2 p; p.x = *(uint32_t*)&h0; p.y = *(uint32_t*)&h1;
            ((uint2*)gA_in)[i] = p;
        }
        {
            float4 a = sf[i];
            __half2 h0 = __floats2half2_rn(a.x, a.y);
            __half2 h1 = __floats2half2_rn(a.z, a.w);
            uint2 p; p.x = *(uint32_t*)&h0; p.y = *(uint32_t*)&h1;
            ((uint2*)gA_sf)[i] = p;
        }
    } else {
        int i = (blockIdx.x - CONV_A_BLOCKS) * 256 + threadIdx.x;  // 1152*64 float4s
        int row = i >> 6, k4 = i & 63;
        float4 a;
        uint2* dst;
        if (row < 256)       { a = Wval [(size_t)row * 64 + k4];         dst = (uint2*)gW_all + i; }
        else if (row < 736)  { a = Woff [(size_t)(row - 256) * 64 + k4]; dst = (uint2*)gW_all + i; }
        else if (row < OPRJ) { a = Wattn[(size_t)(row - 736) * 64 + k4]; dst = (uint2*)gW_all + i; }
        else                 { a = Wout [(size_t)(row - OPRJ) * 64 + k4];
                               dst = (uint2*)gW_out + ((size_t)(row - OPRJ) * 64 + k4); }
        __half2 h0 = __floats2half2_rn(a.x, a.y);
        __half2 h1 = __floats2half2_rn(a.z, a.w);
        uint2 p; p.x = *(uint32_t*)&h0; p.y = *(uint32_t*)&h1;
        *dst = p;
    }
}

// ---------------------------------------------------------------------------
// fp16 tensor-core GEMM: BM=64, BN=64, BK=32, 3-stage cp.async pipeline,
// 128 threads (4 warps, 2x2 warp grid, warp tile 32x32). ~7 CTAs/SM.
// Vectorized epilogue: (e, e+1) accumulator pairs are contiguous in o for
// every destination -> __half2 (val) / float2 (off, logit, Cout) stores.
// MODE 0 (projection, O=896), MODE 1 (output, O=256).
// ---------------------------------------------------------------------------
template <int MODE>
__global__ __launch_bounds__(128) void gemm_f16(
    const __half* __restrict__ A0, const __half* __restrict__ A1,
    const __half* __restrict__ W,
    const float* __restrict__ bias_val, const float* __restrict__ bias_off,
    const float* __restrict__ bias_attn,
    float* __restrict__ Cout, int M, int O)
{
    constexpr int AST = 40;   // half row stride (32 + 8 pad)
    __shared__ __half As[3][64 * AST];
    __shared__ __half Bs[3][64 * AST];

    const int tid  = threadIdx.x;
    const int warp = tid >> 5;
    const int lane = tid & 31;
    const int warpM = warp >> 1;      // 0..1 (32 rows each)
    const int warpN = warp & 1;       // 0..1 (32 cols each)
    const int row0 = blockIdx.y * 64;
    const int col0 = blockIdx.x * 64;

    const __half* __restrict__ A = (MODE == 0 && col0 >= 256) ? A1 : A0;

    const uint32_t sAs = (uint32_t)__cvta_generic_to_shared(&As[0][0]);
    const uint32_t sBs = (uint32_t)__cvta_generic_to_shared(&Bs[0][0]);
    constexpr uint32_t STAGE = 64 * AST * 2;   // bytes per stage

    auto load_stage = [&](int kt, int s) {
        const int k0 = kt * 32;
#pragma unroll
        for (int p = 0; p < 2; p++) {
            int idx = tid + p * 128;
            int r = idx >> 2, c = idx & 3;
            int gm = row0 + r;
            const __half* src = A + (size_t)(gm < M ? gm : M - 1) * Kin + k0 + c * 8;
            uint32_t dst = sAs + s * STAGE + (uint32_t)(r * AST + c * 8) * 2;
            cp16(dst, src, (gm < M) ? 16 : 0);
        }
#pragma unroll
        for (int p = 0; p < 2; p++) {
            int idx = tid + p * 128;
            int r = idx >> 2, c = idx & 3;
            int go = col0 + r;
            const __half* src = W + (size_t)(go < O ? go : O - 1) * Kin + k0 + c * 8;
            uint32_t dst = sBs + s * STAGE + (uint32_t)(r * AST + c * 8) * 2;
            cp16(dst, src, (go < O) ? 16 : 0);
        }
    };

    float acc[2][4][4] = {};

    load_stage(0, 0); cp_commit();
    load_stage(1, 1); cp_commit();

    constexpr int NKT = Kin / 32;   // 8
    for (int kt = 0; kt < NKT; kt++) {
        const int s = kt % 3;
        if (kt + 2 < NKT) load_stage(kt + 2, (kt + 2) % 3);
        cp_commit();
        cp_wait2();
        __syncthreads();

        const uint32_t aBase = sAs + s * STAGE;
        const uint32_t bBase = sBs + s * STAGE;
#pragma unroll
        for (int h = 0; h < 2; h++) {
            uint32_t afr[2][4], bfr[2][4];
#pragma unroll
            for (int mt = 0; mt < 2; mt++) {
                uint32_t addr = aBase +
                    (uint32_t)((warpM * 32 + mt * 16 + (lane & 15)) * AST +
                               h * 16 + (lane >> 4) * 8) * 2;
                ldsm4(afr[mt], addr);
            }
#pragma unroll
            for (int nt2 = 0; nt2 < 2; nt2++) {
                uint32_t addr = bBase +
                    (uint32_t)((warpN * 32 + nt2 * 16 + (lane & 15)) * AST +
                               h * 16 + (lane >> 4) * 8) * 2;
                ldsm4(bfr[nt2], addr);
            }
#pragma unroll
            for (int mt = 0; mt < 2; mt++)
#pragma unroll
                for (int nt = 0; nt < 4; nt++) {
                    uint32_t b0 = (nt & 1) ? bfr[nt >> 1][1] : bfr[nt >> 1][0];
                    uint32_t b1 = (nt & 1) ? bfr[nt >> 1][3] : bfr[nt >> 1][2];
                    mma16816(acc[mt][nt], afr[mt], b0, b1);
                }
        }
        __syncthreads();
    }

    // Vectorized epilogue: pairs (e=0,1) and (e=2,3) contiguous in o.
#pragma unroll
    for (int mt = 0; mt < 2; mt++) {
#pragma unroll
        for (int nt = 0; nt < 4; nt++) {
#pragma unroll
            for (int ep = 0; ep < 2; ep++) {          // element pair
                int m = row0 + warpM * 32 + mt * 16 + (lane >> 2) + ep * 8;
                int o = col0 + warpN * 32 + nt * 8 + 2 * (lane & 3);  // even
                if (m >= M || o >= O) continue;
                float v0 = acc[mt][nt][ep * 2 + 0];
                float v1 = acc[mt][nt][ep * 2 + 1];
                if (MODE == 0) {
                    if (o < 256) {
                        int b = m / Sc, ss = m % Sc;
                        int hh = o >> 5, d = o & 31;  // d even, d+1 same head
                        __half2 hv = __floats2half2_rn(v0 + bias_val[o],
                                                       v1 + bias_val[o + 1]);
                        *(__half2*)&g_valh[(((size_t)(b * Hc + hh)) * Sc + ss) * 32 + d] = hv;
                    } else if (o < 736) {
                        float2 f = make_float2(v0 + bias_off[o - 256],
                                               v1 + bias_off[o - 255]);
                        *(float2*)&g_off[(size_t)m * OFFC + (o - 256)] = f;
                    } else {
                        float2 f = make_float2(v0 + bias_attn[o - 736],
                                               v1 + bias_attn[o - 735]);
                        *(float2*)&g_logit[(size_t)m * ATTC + (o - 736)] = f;
                    }
                } else {
                    float2 f = make_float2(v0 + bias_val[o], v1 + bias_val[o + 1]);
                    *(float2*)&Cout[(size_t)m * O + o] = f;
                }
            }
        }
    }
}

// ---------------------------------------------------------------------------
// Fused sampler (unchanged from R13: __launch_bounds__(256, 8), FFMA2,
// single-exp softmax). Converged at ~90us, L1-wavefront bound.
// ---------------------------------------------------------------------------
__global__ __launch_bounds__(256, 8) void sample_kernel(
    const float* __restrict__ priors,
    const int* __restrict__ map_shapes,
    const int* __restrict__ start_ids)
{
    const int m = blockIdx.x;
    const int b = (m >= Nn) ? 1 : 0;

    __shared__ int2  s_tab[ATTC][8];
    __shared__ float s_logit[ATTC];
    __shared__ float s_exp[ATTC];
    __shared__ float s_wh[Lc][2];
    __shared__ int   s_start[Lc];

    const int tid = threadIdx.x;
    if (tid < Lc) {
        s_wh[tid][0] = (float)map_shapes[tid * 2 + 1];  // W
        s_wh[tid][1] = (float)map_shapes[tid * 2 + 0];  // H
        s_start[tid] = start_ids[tid];
    }
    for (int i = tid; i < ATTC; i += 256) s_logit[i] = g_logit[(size_t)m * ATTC + i];
    __syncthreads();

    if (tid < ATTC) {
        const int h = tid / NPT;
        float mx = -1e30f;
        for (int j = 0; j < NPT; j++) mx = fmaxf(mx, s_logit[h * NPT + j]);
        s_exp[tid] = __expf(s_logit[tid] - mx);
    }
    __syncthreads();

    if (tid < ATTC) {
        const int h  = tid / NPT;
        const int lp = tid % NPT;
        const int l  = lp / Pc;
        const float ox = g_off[(size_t)m * OFFC + tid * 3 + 0];
        const float oy = g_off[(size_t)m * OFFC + tid * 3 + 1];
        const float oz = g_off[(size_t)m * OFFC + tid * 3 + 2];
        const float Wl = s_wh[l][0], Hl = s_wh[l][1];
        const float px = priors[((size_t)m * Lc + l) * 2 + 0];
        const float py = priors[((size_t)m * Lc + l) * 2 + 1];
        const float lx = px + ox / Wl;
        const float ly = py + oy / Hl;
        const float lz = (float)l * (1.0f / (Lc - 1)) + oz;

        float sum = 0.f;
        for (int j = 0; j < NPT; j++) sum += s_exp[h * NPT + j];
        const float a = s_exp[tid] / sum;

        float z = fminf(fmaxf(lz, 0.f), 1.f) * (float)(Lc - 1);
        int z0 = min((int)z, Lc - 2);
        float wz = z - (float)z0;

#pragma unroll
        for (int q = 0; q < 2; q++) {
            const int lvl = z0 + q;
            const float wl = a * (q ? wz : (1.f - wz));
            const float Wf = s_wh[lvl][0], Hf = s_wh[lvl][1];
            const int Wi = (int)Wf, Hi = (int)Hf;
            const int offb = s_start[lvl];
            const float x = lx * Wf - 0.5f;
            const float y = ly * Hf - 0.5f;
            const float x0f = floorf(x), y0f = floorf(y);
            const float dx = x - x0f, dy = y - y0f;
            const int x0 = (int)x0f, y0 = (int)y0f;

            const float cw[4] = {(1.f - dx) * (1.f - dy), dx * (1.f - dy),
                                 (1.f - dx) * dy,          dx * dy};
            const int cx[4] = {x0, x0 + 1, x0, x0 + 1};
            const int cy[4] = {y0, y0, y0 + 1, y0 + 1};
#pragma unroll
            for (int c = 0; c < 4; c++) {
                const bool valid = (cx[c] >= 0) & (cx[c] < Wi) & (cy[c] >= 0) & (cy[c] < Hi);
                const int idx = valid ? (offb + cy[c] * Wi + cx[c]) : 0;
                const float w = valid ? (wl * cw[c]) : 0.f;
                s_tab[tid][q * 4 + c] = make_int2(idx << 6, __float_as_int(w));
            }
        }
    }
    __syncthreads();

    const int warp = tid >> 5;              // head
    const int lane = tid & 31;
    const int sub  = lane >> 2;             // corner 0..7
    const int ch   = lane & 3;              // 16B channel group

    const char* __restrict__ vbase =
        (const char*)g_valh + (size_t)(b * Hc + warp) * Sc * 64 + ch * 16;

    float2 acc[4] = {};
#pragma unroll
    for (int p = 0; p < NPT; p++) {
        const int2 e = s_tab[warp * NPT + p][sub];
        const float w = __int_as_float(e.y);
        if (w != 0.f) {
            const uint4 raw = __ldg((const uint4*)(vbase + e.x));
            const float2 wv = make_float2(w, w);
            ffma2(acc[0], __half22float2(*(const __half2*)&raw.x), wv);
            ffma2(acc[1], __half22float2(*(const __half2*)&raw.y), wv);
            ffma2(acc[2], __half22float2(*(const __half2*)&raw.z), wv);
            ffma2(acc[3], __half22float2(*(const __half2*)&raw.w), wv);
        }
    }
#pragma unroll
    for (int d = 4; d < 32; d <<= 1) {
#pragma unroll
        for (int j = 0; j < 4; j++) {
            acc[j].x += __shfl_xor_sync(0xFFFFFFFFu, acc[j].x, d);
            acc[j].y += __shfl_xor_sync(0xFFFFFFFFu, acc[j].y, d);
        }
    }
    if (lane < 4) {
        __half2 h0 = __floats2half2_rn(acc[0].x, acc[0].y);
        __half2 h1 = __floats2half2_rn(acc[1].x, acc[1].y);
        __half2 h2 = __floats2half2_rn(acc[2].x, acc[2].y);
        __half2 h3 = __floats2half2_rn(acc[3].x, acc[3].y);
        uint4 pack;
        pack.x = *(uint32_t*)&h0;
        pack.y = *(uint32_t*)&h1;
        pack.z = *(uint32_t*)&h2;
        pack.w = *(uint32_t*)&h3;
        ((uint4*)gA_w)[(size_t)m * 32 + warp * 4 + ch] = pack;
    }
}

// ---------------------------------------------------------------------------
// kernel_launch
// ---------------------------------------------------------------------------
extern "C" void kernel_launch(void* const* d_in, const int* in_sizes, int n_in,
                              void* d_out, int out_size)
{
    const float* in_feats  = (const float*)d_in[0];
    const float* priors    = (const float*)d_in[1];
    const float* sfeats    = (const float*)d_in[2];
    const float* W_off     = (const float*)d_in[3];
    const float* b_off     = (const float*)d_in[4];
    const float* W_attn    = (const float*)d_in[5];
    const float* b_attn    = (const float*)d_in[6];
    const float* W_val     = (const float*)d_in[7];
    const float* b_val     = (const float*)d_in[8];
    const float* W_out     = (const float*)d_in[9];
    const float* b_out     = (const float*)d_in[10];
    const int*   shapes    = (const int*)d_in[11];
    const int*   start_ids = (const int*)d_in[12];

    __half *pA_in, *pA_sf, *pA_w, *pW_all, *pW_out;
    cudaGetSymbolAddress((void**)&pA_in,  gA_in);
    cudaGetSymbolAddress((void**)&pA_sf,  gA_sf);
    cudaGetSymbolAddress((void**)&pA_w,   gA_w);
    cudaGetSymbolAddress((void**)&pW_all, gW_all);
    cudaGetSymbolAddress((void**)&pW_out, gW_out);

    // fp32 -> fp16 conversions (activations + weights, one launch)
    conv_all<<<CONV_A_BLOCKS + CONV_W_BLOCKS, 256>>>(
        (const float4*)in_feats, (const float4*)sfeats,
        (const float4*)W_val, (const float4*)W_off,
        (const float4*)W_attn, (const float4*)W_out);

    const int gridM = (Mtot + 63) / 64;   // 171

    // Combined projection GEMM: [val | off | attn], O=896
    gemm_f16<0><<<dim3(OPRJ / 64, gridM), 128>>>(
        pA_sf, pA_in, pW_all, b_val, b_off, b_attn, nullptr, Mtot, OPRJ);
    // Fused sampler -> gA_w (fp16)
    sample_kernel<<<Mtot, 256>>>(priors, shapes, start_ids);
    // Output projection -> d_out (fp32)
    gemm_f16<1><<<dim3(4, gridM), 128>>>(
        pA_w, nullptr, pW_out, b_out, nullptr, nullptr, (float*)d_out, Mtot, 256);
}